// round 8
// baseline (speedup 1.0000x reference)
#include <cuda_runtime.h>
#include <math.h>
#include <stdint.h>

#define LSEQ 2048
#define BATCH 2
#define EMB 512
#define NH 8
#define HD 64
#define NHEAD 16  // BATCH*NH

#define NX (LSEQ * BATCH * EMB)  // 2097152
#define NWI (3 * EMB * EMB)      // 786432
#define NWO (EMB * EMB)          // 262144
#define NER (LSEQ * HD)          // 131072

// interleave-within-8: order [0,4,1,5,2,6,3,7]; pairs (j, j+4) adjacent
#define ILV(d) (((d) & ~7) | (((d) & 3) << 1) | (((d) >> 2) & 1))

// Scratch (device globals; allocation-free per harness rules)
__device__ __align__(16) float g_q[NHEAD * LSEQ * HD];   // [h][l][d_ilv]
__device__ __align__(16) float g_k[NHEAD * LSEQ * HD];   // [h][l][d_ilv]
__device__ __align__(16) float g_v[NHEAD * LSEQ * HD];   // TRANSPOSED: [h][d][l_ilv]
__device__ __align__(16) float g_o[NHEAD * LSEQ * HD];   // [h][l][d] plain
__device__ __align__(16) float g_R[(size_t)NHEAD * LSEQ * LSEQ + 16];  // 256 MiB
// RNA-prerounded inputs (cp.async feeds exact tf32 to mma)
__device__ __align__(16) float g_xr[NX];
__device__ __align__(16) float g_wir[NWI];
__device__ __align__(16) float g_wor[NWO];
__device__ __align__(16) float g_er[NER];                // [m][d_ilv]

__device__ __forceinline__ float to_tf32(float x) {
    uint32_t y;
    asm("cvt.rna.tf32.f32 %0, %1;" : "=r"(y) : "f"(x));
    return __uint_as_float(y);
}

__device__ __forceinline__ void mma8(float d[4], uint32_t a0, uint32_t a1,
                                     uint32_t a2, uint32_t a3,
                                     uint32_t b0, uint32_t b1) {
    asm volatile(
        "mma.sync.aligned.m16n8k8.row.col.f32.tf32.tf32.f32 "
        "{%0,%1,%2,%3}, {%4,%5,%6,%7}, {%8,%9}, {%0,%1,%2,%3};\n"
        : "+f"(d[0]), "+f"(d[1]), "+f"(d[2]), "+f"(d[3])
        : "r"(a0), "r"(a1), "r"(a2), "r"(a3), "r"(b0), "r"(b1));
}

__device__ __forceinline__ void cp16(uint32_t dst, const void* src) {
    asm volatile("cp.async.cg.shared.global [%0], [%1], 16;\n" ::"r"(dst), "l"(src));
}
__device__ __forceinline__ void cp_commit() { asm volatile("cp.async.commit_group;\n"); }
__device__ __forceinline__ void cp_wait0() { asm volatile("cp.async.wait_group 0;\n" ::: "memory"); }
__device__ __forceinline__ void cp_wait1() { asm volatile("cp.async.wait_group 1;\n" ::: "memory"); }

// ---------------------------------------------------------------------------
// Kernel 0: RNA-preround inputs into scratch. Er additionally d-interleaved.
// ---------------------------------------------------------------------------
__global__ void __launch_bounds__(256) preround(const float4* __restrict__ x,
                                                const float4* __restrict__ Wi,
                                                const float4* __restrict__ Wo,
                                                const float4* __restrict__ Er) {
    int i = blockIdx.x * 256 + threadIdx.x;  // grid sized exactly
    if (i < NX / 4) {
        float4 v = x[i];
        v.x = to_tf32(v.x); v.y = to_tf32(v.y); v.z = to_tf32(v.z); v.w = to_tf32(v.w);
        ((float4*)g_xr)[i] = v;
    } else if (i < (NX + NWI) / 4) {
        int j = i - NX / 4;
        float4 v = Wi[j];
        v.x = to_tf32(v.x); v.y = to_tf32(v.y); v.z = to_tf32(v.z); v.w = to_tf32(v.w);
        ((float4*)g_wir)[j] = v;
    } else if (i < (NX + NWI + NWO) / 4) {
        int j = i - (NX + NWI) / 4;
        float4 v = Wo[j];
        v.x = to_tf32(v.x); v.y = to_tf32(v.y); v.z = to_tf32(v.z); v.w = to_tf32(v.w);
        ((float4*)g_wor)[j] = v;
    } else {
        int j = i - (NX + NWI + NWO) / 4;
        float4 v = Er[j];
        int base = j * 4;
        int m = base >> 6, d0 = base & 63;
        g_er[(m << 6) | ILV(d0 + 0)] = to_tf32(v.x);
        g_er[(m << 6) | ILV(d0 + 1)] = to_tf32(v.y);
        g_er[(m << 6) | ILV(d0 + 2)] = to_tf32(v.z);
        g_er[(m << 6) | ILV(d0 + 3)] = to_tf32(v.w);
    }
}

#define GS (128 * 36)  // one 128-row GEMM stage (floats); stride 36 = conflict-free

// One BK=32 stage. 8 warps as 4(m)x2(n); warp tile 32 x (NF*8).
template <int NF>
__device__ __forceinline__ void gemm_stage(const float* A, const float* B,
                                           float acc[2][NF][4], int wm, int wn,
                                           int rq, int t4) {
#pragma unroll
    for (int ks = 0; ks < 4; ks++) {
        uint32_t bf[NF][2];
#pragma unroll
        for (int nf = 0; nf < NF; nf++) {
            const float* bp = B + (wn * NF * 8 + nf * 8 + rq) * 36 + ks * 8 + t4;
            bf[nf][0] = __float_as_uint(bp[0]);
            bf[nf][1] = __float_as_uint(bp[4]);
        }
#pragma unroll
        for (int mf = 0; mf < 2; mf++) {
            const float* ap = A + (wm * 32 + mf * 16 + rq) * 36 + ks * 8 + t4;
            uint32_t a0 = __float_as_uint(ap[0]);
            uint32_t a1 = __float_as_uint(ap[8 * 36]);
            uint32_t a2 = __float_as_uint(ap[4]);
            uint32_t a3 = __float_as_uint(ap[8 * 36 + 4]);
#pragma unroll
            for (int nf = 0; nf < NF; nf++)
                mma8(acc[mf][nf], a0, a1, a2, a3, bf[nf][0], bf[nf][1]);
        }
    }
}

// ---------------------------------------------------------------------------
// Kernel 1: qkv = xr @ Wir^T + b -> scatter head-major (q scaled), tf32-rounded.
// q/k stored d-interleaved; v stored transposed [h][d][l_ilv].
// ---------------------------------------------------------------------------
__global__ void __launch_bounds__(256, 2) gemm_qkv(const float* __restrict__ bias) {
    extern __shared__ float sm[];
    float* As = sm;
    float* Bs = sm + 2 * GS;
    const int tid = threadIdx.x, lane = tid & 31, warp = tid >> 5;
    const int wm = warp >> 1, wn = warp & 1;
    const int rq = lane >> 2, t4 = lane & 3;
    const int r0 = blockIdx.x * 128, c0 = blockIdx.y * 128;
    const int arow = tid >> 3, achk = (tid & 7) * 4;
    uint32_t sA = (uint32_t)__cvta_generic_to_shared(As);
    uint32_t sB = (uint32_t)__cvta_generic_to_shared(Bs);
    float acc[2][8][4] = {};

    auto prefetch = [&](int st, int kt) {
        int k0 = kt * 32;
#pragma unroll
        for (int p = 0; p < 4; p++) {
            int row = p * 32 + arow;
            cp16(sA + (st * GS + row * 36 + achk) * 4,
                 g_xr + (size_t)(r0 + row) * EMB + k0 + achk);
            cp16(sB + (st * GS + row * 36 + achk) * 4,
                 g_wir + (size_t)(c0 + row) * EMB + k0 + achk);
        }
    };

    prefetch(0, 0);
    cp_commit();
    const int nk = EMB / 32;
    for (int kt = 0; kt < nk; kt++) {
        if (kt + 1 < nk) {
            prefetch((kt + 1) & 1, kt + 1);
            cp_commit();
            cp_wait1();
        } else {
            cp_wait0();
        }
        __syncthreads();
        gemm_stage<8>(As + (kt & 1) * GS, Bs + (kt & 1) * GS, acc, wm, wn, rq, t4);
        __syncthreads();
    }

#pragma unroll
    for (int mf = 0; mf < 2; mf++)
#pragma unroll
        for (int nf = 0; nf < 8; nf++)
#pragma unroll
            for (int j = 0; j < 4; j++) {
                int r = r0 + wm * 32 + mf * 16 + rq + (j >> 1) * 8;
                int c = c0 + wn * 64 + nf * 8 + 2 * t4 + (j & 1);
                float val = acc[mf][nf][j] + bias[c];
                int l = r >> 1, b = r & 1;
                int part = c >> 9;
                int cc = c & 511;
                int h = cc >> 6, d = cc & 63;
                int hb = b * NH + h;
                if (part == 0)
                    g_q[((size_t)hb * LSEQ + l) * HD + ILV(d)] = to_tf32(val) * 0.125f;
                else if (part == 1)
                    g_k[((size_t)hb * LSEQ + l) * HD + ILV(d)] = to_tf32(val);
                else
                    g_v[((size_t)hb * HD + d) * LSEQ + ILV(l)] = to_tf32(val);
            }
}

// ---------------------------------------------------------------------------
// Kernel 2: R[h,l,c] = q[h,l,:] . er[c,:]. Flash reads columns c = 2047-l+m
// (m<=l) => upper-right block band: tiles with bx+by >= 15 ONLY.
// (q and er are both d-interleaved: dot products unchanged.)
// ---------------------------------------------------------------------------
__global__ void __launch_bounds__(256, 2) gemm_rel() {
    if (blockIdx.x + blockIdx.y < 15) return;  // needed band is upper-right
    extern __shared__ float sm[];
    float* As = sm;
    float* Bs = sm + 2 * GS;
    const int tid = threadIdx.x, lane = tid & 31, warp = tid >> 5;
    const int wm = warp >> 1, wn = warp & 1;
    const int rq = lane >> 2, t4 = lane & 3;
    const int l0 = blockIdx.x * 128, c0 = blockIdx.y * 128;
    const int h = blockIdx.z;
    const float* q = g_q + (size_t)h * LSEQ * HD;
    const int arow = tid >> 3, achk = (tid & 7) * 4;
    uint32_t sA = (uint32_t)__cvta_generic_to_shared(As);
    uint32_t sB = (uint32_t)__cvta_generic_to_shared(Bs);
    float acc[2][8][4] = {};

#pragma unroll
    for (int st = 0; st < 2; st++) {
        int k0 = st * 32;
#pragma unroll
        for (int p = 0; p < 4; p++) {
            int row = p * 32 + arow;
            cp16(sA + (st * GS + row * 36 + achk) * 4,
                 q + (size_t)(l0 + row) * HD + k0 + achk);
            cp16(sB + (st * GS + row * 36 + achk) * 4,
                 g_er + (size_t)(c0 + row) * HD + k0 + achk);
        }
        cp_commit();
    }
    cp_wait0();
    __syncthreads();
    gemm_stage<8>(As, Bs, acc, wm, wn, rq, t4);
    gemm_stage<8>(As + GS, Bs + GS, acc, wm, wn, rq, t4);

#pragma unroll
    for (int mf = 0; mf < 2; mf++)
#pragma unroll
        for (int nf = 0; nf < 8; nf++)
#pragma unroll
            for (int j = 0; j < 4; j++) {
                int l = l0 + wm * 32 + mf * 16 + rq + (j >> 1) * 8;
                int m = c0 + wn * 64 + nf * 8 + 2 * t4 + (j & 1);
                g_R[((size_t)h * LSEQ + l) * LSEQ + m] = acc[mf][nf][j];
            }
}

// ---------------------------------------------------------------------------
// Kernel 3: fused flash attention + skewed rel add. BM=128 (8 warps x 16 rows),
// BN=64. Q frags register-resident; K/V cp.async x2. All fragment loads are
// LDS.64 thanks to the interleaved layouts. P C->A frag via quad shfl.
// ---------------------------------------------------------------------------
#define FS (64 * 72)
__global__ void __launch_bounds__(256, 2) flash_attn() {
    extern __shared__ float sm[];
    float* Ks = sm;               // [2][64*72]; also Q staging (128*72 = 2*FS)
    float* Vs = sm + 2 * FS;      // [2][64*72]  V^T tile: [d][m_ilv]

    const int tid = threadIdx.x, lane = tid & 31, warp = tid >> 5;
    const int rq = lane >> 2, t4 = lane & 3;
    const int h = blockIdx.y;
    const int l0 = blockIdx.x * 128;
    const float* qg = g_q + (size_t)h * LSEQ * HD;
    const float* kg = g_k + (size_t)h * LSEQ * HD;
    const float* vg = g_v + (size_t)h * HD * LSEQ;  // transposed
    uint32_t sK = (uint32_t)__cvta_generic_to_shared(Ks);
    uint32_t sV = (uint32_t)__cvta_generic_to_shared(Vs);

    // stage Q (128x64) into the K region, extract fragments, then release
#pragma unroll
    for (int p = 0; p < 8; p++) {
        int cg = tid * 8 + p;
        int row = cg >> 4, c4 = (cg & 15) * 4;
        cp16(sK + (row * 72 + c4) * 4, qg + (size_t)(l0 + row) * HD + c4);
    }
    cp_commit();
    cp_wait0();
    __syncthreads();

    uint32_t qf[8][4];
    {
        const float* base = Ks + (warp * 16 + rq) * 72;
#pragma unroll
        for (int ks = 0; ks < 8; ks++) {
            float2 lo = *(const float2*)(base + ks * 8 + 2 * t4);
            float2 hi = *(const float2*)(base + 8 * 72 + ks * 8 + 2 * t4);
            qf[ks][0] = __float_as_uint(lo.x);
            qf[ks][2] = __float_as_uint(lo.y);
            qf[ks][1] = __float_as_uint(hi.x);
            qf[ks][3] = __float_as_uint(hi.y);
        }
    }
    __syncthreads();  // all warps done reading Q before KV prefetch overwrites

    auto pre_kv = [&](int st, int kt) {
        int m0 = kt * 64;
#pragma unroll
        for (int p = 0; p < 4; p++) {
            int cg = tid * 4 + p;
            int row = cg >> 4, c4 = (cg & 15) * 4;
            cp16(sK + (st * FS + row * 72 + c4) * 4,
                 kg + (size_t)(m0 + row) * HD + c4);
            cp16(sV + (st * FS + row * 72 + c4) * 4,
                 vg + (size_t)row * LSEQ + m0 + c4);  // row = d, c4 = m offset
        }
    };
    pre_kv(0, 0);
    cp_commit();

    const int row_lo = warp * 16 + rq;
    const int src1 = (lane & ~3) | (t4 >> 1);
    const int src2 = src1 + 2;
    const bool odd = t4 & 1;
    float Mi[2] = {-1e30f, -1e30f};
    float Si[2] = {0.f, 0.f};
    float o[8][4] = {};

    for (int kt = 0; kt < 32; kt++) {
        const int m0 = kt * 64;
        if (kt + 1 < 32) {
            pre_kv((kt + 1) & 1, kt + 1);
            cp_commit();
            cp_wait1();
        } else {
            cp_wait0();
        }
        __syncthreads();
        const float* K = Ks + (kt & 1) * FS;
        const float* V = Vs + (kt & 1) * FS;

        // S = Q @ K^T  (all B frags are single LDS.64)
        float s[8][4] = {};
#pragma unroll
        for (int ks = 0; ks < 8; ks++) {
#pragma unroll
            for (int nc = 0; nc < 8; nc++) {
                float2 b = *(const float2*)(K + (nc * 8 + rq) * 72 + ks * 8 + 2 * t4);
                mma8(s[nc], qf[ks][0], qf[ks][1], qf[ks][2], qf[ks][3],
                     __float_as_uint(b.x), __float_as_uint(b.y));
            }
        }

        // + skewed relative scores (band tiles only)
        if (m0 <= l0 + 127) {
#pragma unroll
            for (int i = 0; i < 2; i++) {
                int l = l0 + row_lo + i * 8;
                const float* Rrow = g_R + ((size_t)h * LSEQ + l) * LSEQ + (2047 - l);
#pragma unroll
                for (int nc = 0; nc < 8; nc++) {
                    int m = m0 + nc * 8 + 2 * t4;
                    if (m <= l) s[nc][2 * i] += Rrow[m];
                    if (m + 1 <= l) s[nc][2 * i + 1] += Rrow[m + 1];
                }
            }
        }

        // online softmax (rows warp-local; quad shfl reductions)
        float mloc[2] = {-1e30f, -1e30f};
#pragma unroll
        for (int nc = 0; nc < 8; nc++) {
            mloc[0] = fmaxf(mloc[0], fmaxf(s[nc][0], s[nc][1]));
            mloc[1] = fmaxf(mloc[1], fmaxf(s[nc][2], s[nc][3]));
        }
#pragma unroll
        for (int off = 1; off < 4; off <<= 1) {
            mloc[0] = fmaxf(mloc[0], __shfl_xor_sync(0xffffffffu, mloc[0], off));
            mloc[1] = fmaxf(mloc[1], __shfl_xor_sync(0xffffffffu, mloc[1], off));
        }
        float newM[2], sc[2], lsum[2] = {0.f, 0.f};
#pragma unroll
        for (int i = 0; i < 2; i++) {
            newM[i] = fmaxf(Mi[i], mloc[i]);
            sc[i] = __expf(Mi[i] - newM[i]);
            Mi[i] = newM[i];
        }
        // P = exp(S - M) kept in C-fragment registers, RNA-tf32
#pragma unroll
        for (int nc = 0; nc < 8; nc++) {
            float p0 = __expf(s[nc][0] - newM[0]);
            float p1 = __expf(s[nc][1] - newM[0]);
            float p2 = __expf(s[nc][2] - newM[1]);
            float p3 = __expf(s[nc][3] - newM[1]);
            lsum[0] += p0 + p1;
            lsum[1] += p2 + p3;
            s[nc][0] = to_tf32(p0); s[nc][1] = to_tf32(p1);
            s[nc][2] = to_tf32(p2); s[nc][3] = to_tf32(p3);
        }
#pragma unroll
        for (int off = 1; off < 4; off <<= 1) {
            lsum[0] += __shfl_xor_sync(0xffffffffu, lsum[0], off);
            lsum[1] += __shfl_xor_sync(0xffffffffu, lsum[1], off);
        }
#pragma unroll
        for (int i = 0; i < 2; i++) Si[i] = Si[i] * sc[i] + lsum[i];
#pragma unroll
        for (int nc = 0; nc < 8; nc++) {
            o[nc][0] *= sc[0]; o[nc][1] *= sc[0];
            o[nc][2] *= sc[1]; o[nc][3] *= sc[1];
        }

        // O += P @ V : P C-frag -> A-frag via quad shuffles; V frags LDS.64
#pragma unroll
        for (int g = 0; g < 8; g++) {
            float v00 = __shfl_sync(0xffffffffu, s[g][0], src1);
            float v01 = __shfl_sync(0xffffffffu, s[g][1], src1);
            float v02 = __shfl_sync(0xffffffffu, s[g][2], src1);
            float v03 = __shfl_sync(0xffffffffu, s[g][3], src1);
            float w00 = __shfl_sync(0xffffffffu, s[g][0], src2);
            float w01 = __shfl_sync(0xffffffffu, s[g][1], src2);
            float w02 = __shfl_sync(0xffffffffu, s[g][2], src2);
            float w03 = __shfl_sync(0xffffffffu, s[g][3], src2);
            uint32_t a0 = __float_as_uint(odd ? v01 : v00);
            uint32_t a1 = __float_as_uint(odd ? v03 : v02);
            uint32_t a2 = __float_as_uint(odd ? w01 : w00);
            uint32_t a3 = __float_as_uint(odd ? w03 : w02);
#pragma unroll
            for (int nc = 0; nc < 8; nc++) {
                float2 b = *(const float2*)(V + (nc * 8 + rq) * 72 + g * 8 + 2 * t4);
                mma8(o[nc], a0, a1, a2, a3,
                     __float_as_uint(b.x), __float_as_uint(b.y));
            }
        }
        __syncthreads();
    }

    float inv[2] = {1.0f / Si[0], 1.0f / Si[1]};
#pragma unroll
    for (int nc = 0; nc < 8; nc++)
#pragma unroll
        for (int j = 0; j < 4; j++) {
            int l = l0 + row_lo + (j >> 1) * 8;
            int d = nc * 8 + 2 * t4 + (j & 1);
            g_o[((size_t)h * LSEQ + l) * HD + d] = to_tf32(o[nc][j] * inv[j >> 1]);
        }
}

// ---------------------------------------------------------------------------
// Kernel 4: out = attn_out @ Wor^T + b. BM=128, BN=64 (grid 256 for occupancy).
// ---------------------------------------------------------------------------
__global__ void __launch_bounds__(256, 2) gemm_out(const float* __restrict__ bout,
                                                   float* __restrict__ out) {
    extern __shared__ float sm[];
    float* As = sm;                 // [2][128*36]
    float* Bs = sm + 2 * GS;        // [2][64*36]
    const int tid = threadIdx.x, lane = tid & 31, warp = tid >> 5;
    const int wm = warp >> 1, wn = warp & 1;
    const int rq = lane >> 2, t4 = lane & 3;
    const int r0 = blockIdx.x * 128, c0 = blockIdx.y * 64;
    const int arow = tid >> 3, achk = (tid & 7) * 4;
    uint32_t sA = (uint32_t)__cvta_generic_to_shared(As);
    uint32_t sB = (uint32_t)__cvta_generic_to_shared(Bs);
    const int BGS = 64 * 36;
    float acc[2][4][4] = {};

    auto prefetch = [&](int st, int kt) {
        int k0 = kt * 32;
#pragma unroll
        for (int p = 0; p < 4; p++) {
            int row = p * 32 + arow;
            int r = r0 + row;
            int l = r >> 1, b = r & 1;
            int e = k0 + achk;
            int hh = e >> 6, d = e & 63;
            cp16(sA + (st * GS + row * 36 + achk) * 4,
                 g_o + ((size_t)(b * NH + hh) * LSEQ + l) * HD + d);
        }
#pragma unroll
        for (int p = 0; p < 2; p++) {
            int row = p * 32 + arow;
            cp16(sB + (st * BGS + row * 36 + achk) * 4,
                 g_wor + (size_t)(c0 + row) * EMB + k0 + achk);
        }
    };

    prefetch(0, 0);
    cp_commit();
    const int nk = EMB / 32;
    for (int kt = 0; kt < nk; kt++) {
        if (kt + 1 < nk) {
            prefetch((kt + 1) & 1, kt + 1);
            cp_commit();
            cp_wait1();
        } else {
            cp_wait0();
        }
        __syncthreads();
        gemm_stage<4>(As + (kt & 1) * GS, Bs + (kt & 1) * BGS, acc, wm, wn, rq, t4);
        __syncthreads();
    }

#pragma unroll
    for (int mf = 0; mf < 2; mf++)
#pragma unroll
        for (int nf = 0; nf < 4; nf++)
#pragma unroll
            for (int j = 0; j < 4; j++) {
                int r = r0 + wm * 32 + mf * 16 + rq + (j >> 1) * 8;
                int c = c0 + wn * 32 + nf * 8 + 2 * t4 + (j & 1);
                out[(size_t)r * EMB + c] = acc[mf][nf][j] + bout[c];
            }
}

// ---------------------------------------------------------------------------
extern "C" void kernel_launch(void* const* d_in, const int* in_sizes, int n_in,
                              void* d_out, int out_size) {
    (void)in_sizes; (void)n_in; (void)out_size;
    const float* x    = (const float*)d_in[0];
    const float* Win  = (const float*)d_in[1];
    const float* bin  = (const float*)d_in[2];
    const float* Wout = (const float*)d_in[3];
    const float* bout = (const float*)d_in[4];
    const float* Er   = (const float*)d_in[5];
    float* out = (float*)d_out;

    const int gemm_smem = 4 * GS * sizeof(float);                      // 73728
    const int out_smem = (2 * GS + 2 * 64 * 36) * sizeof(float);       // 55296
    const int flash_smem = 4 * FS * sizeof(float);                     // 73728

    cudaFuncSetAttribute(gemm_qkv, cudaFuncAttributeMaxDynamicSharedMemorySize, gemm_smem);
    cudaFuncSetAttribute(gemm_rel, cudaFuncAttributeMaxDynamicSharedMemorySize, gemm_smem);
    cudaFuncSetAttribute(gemm_out, cudaFuncAttributeMaxDynamicSharedMemorySize, out_smem);
    cudaFuncSetAttribute(flash_attn, cudaFuncAttributeMaxDynamicSharedMemorySize, flash_smem);

    preround<<<(NX + NWI + NWO + NER) / 4 / 256, 256>>>(
        (const float4*)x, (const float4*)Win, (const float4*)Wout, (const float4*)Er);
    gemm_qkv<<<dim3(32, 12), 256, gemm_smem>>>(bin);
    gemm_rel<<<dim3(16, 16, 16), 256, gemm_smem>>>();
    flash_attn<<<dim3(16, 16), 256, flash_smem>>>();
    gemm_out<<<dim3(32, 8), 256, out_smem>>>(bout, out);
}